// round 5
// baseline (speedup 1.0000x reference)
#include <cuda_runtime.h>

// ---------------------------------------------------------------------------
// GCNMixEncoder: 3-layer graph propagation + layer-mean + batched gather.
// R5: R4 (passing, 386us) + packed int2 edges + SpMM inner loop unroll x8
// for deeper memory-level parallelism against L2 hit latency.
// ---------------------------------------------------------------------------

#define U_COUNT 100000
#define I_COUNT 50000
#define NN      (U_COUNT + I_COUNT)   // 150000
#define NNZ_C   1600000
#define BATCHQ  4096
#define SCAN_CHUNK 4096
#define N_PAD   151552                 // ceil(NN/4096)*4096
#define NBLK_SCAN (N_PAD / SCAN_CHUNK) // 37

__device__ float g_X[(long long)NN * 128];
__device__ float g_Y[(long long)NN * 128];
__device__ int   g_counts[N_PAD];
__device__ int   g_rowptr[NN + 1];
__device__ int   g_cursor[NN];
__device__ int   g_bsums[64];
__device__ int2  g_edges[NNZ_C];       // {col, float_as_int(val)}

__global__ void k_zero_counts() {
    int i = blockIdx.x * blockDim.x + threadIdx.x;
    if (i < N_PAD) g_counts[i] = 0;
}

__global__ void k_hist(const int* __restrict__ rows) {
    int e = blockIdx.x * blockDim.x + threadIdx.x;
    if (e < NNZ_C) atomicAdd(&g_counts[rows[e]], 1);
}

// Phase 1: block-local exclusive scan of a 4096-elem chunk; total to g_bsums.
__global__ void k_scan_part() {
    __shared__ int wsum[32];
    int b = blockIdx.x, t = threadIdx.x, lane = t & 31, wid = t >> 5;
    int i0 = b * SCAN_CHUNK + t * 4;
    int4 c = *reinterpret_cast<const int4*>(&g_counts[i0]);
    int p1 = c.x;
    int p2 = p1 + c.y;
    int p3 = p2 + c.z;
    int tot = p3 + c.w;
    int v = tot;
    #pragma unroll
    for (int o = 1; o < 32; o <<= 1) {
        int n = __shfl_up_sync(0xffffffffu, v, o);
        if (lane >= o) v += n;
    }
    if (lane == 31) wsum[wid] = v;
    __syncthreads();
    if (wid == 0) {
        int wv = wsum[lane];
        #pragma unroll
        for (int o = 1; o < 32; o <<= 1) {
            int n = __shfl_up_sync(0xffffffffu, wv, o);
            if (lane >= o) wv += n;
        }
        wsum[lane] = wv;
    }
    __syncthreads();
    int warp_off = wid ? wsum[wid - 1] : 0;
    int excl = warp_off + (v - tot);
    if (i0     < NN) g_rowptr[i0]     = excl;
    if (i0 + 1 < NN) g_rowptr[i0 + 1] = excl + p1;
    if (i0 + 2 < NN) g_rowptr[i0 + 2] = excl + p2;
    if (i0 + 3 < NN) g_rowptr[i0 + 3] = excl + p3;
    if (t == 0) g_bsums[b] = wsum[31];
}

// Phase 2: add inter-block offsets (serial sum over <=37 values) + init cursor.
__global__ void k_scan_add() {
    __shared__ int s_off;
    int b = blockIdx.x, t = threadIdx.x;
    if (t == 0) {
        int s = 0;
        for (int j = 0; j < b; ++j) s += g_bsums[j];
        s_off = s;
    }
    __syncthreads();
    int off = s_off;
    int i0 = b * SCAN_CHUNK + t * 4;
    #pragma unroll
    for (int k = 0; k < 4; ++k) {
        int i = i0 + k;
        if (i < NN) {
            int r = g_rowptr[i] + off;
            g_rowptr[i] = r;
            g_cursor[i] = r;
        }
    }
    if (b == 0 && t == 0) g_rowptr[NN] = NNZ_C;
}

__global__ void k_scatter(const int* __restrict__ rows, const int* __restrict__ cols,
                          const float* __restrict__ vals) {
    int e = blockIdx.x * blockDim.x + threadIdx.x;
    if (e >= NNZ_C) return;
    int r = rows[e];
    int p = atomicAdd(&g_cursor[r], 1);
    g_edges[p] = make_int2(cols[e], __float_as_int(vals[e]));
}

// ---------------------------------------------------------------------------
// Warp-per-row CSR SpMM. mode selects source/destination:
//   mode 0: src = [user_emb ; item_emb] (split inputs), dst = g_Y
//   mode 1: src = g_Y, dst = g_X
//   mode 2: src = g_X, dst = g_Y
// Inner loop unrolled x8: 8 independent 16B/lane row fetches in flight.
// ---------------------------------------------------------------------------
__global__ void k_spmm(const float4* __restrict__ embU, const float4* __restrict__ embI,
                       int mode) {
    int w = (blockIdx.x * blockDim.x + threadIdx.x) >> 5;
    int lane = threadIdx.x & 31;
    if (w >= NN) return;

    const float4* srcU;
    const float4* srcI;
    int split;
    float4* dst;
    if (mode == 0) {
        srcU = embU; srcI = embI; split = U_COUNT;
        dst = reinterpret_cast<float4*>(g_Y);
    } else if (mode == 1) {
        srcU = reinterpret_cast<const float4*>(g_Y); srcI = srcU; split = NN;
        dst = reinterpret_cast<float4*>(g_X);
    } else {
        srcU = reinterpret_cast<const float4*>(g_X); srcI = srcU; split = NN;
        dst = reinterpret_cast<float4*>(g_Y);
    }

    int start = g_rowptr[w], end = g_rowptr[w + 1];
    float4 acc = make_float4(0.f, 0.f, 0.f, 0.f);
    for (int base = start; base < end; base += 32) {
        int e = base + lane;
        long long ed = 0;
        if (e < end) ed = *reinterpret_cast<const long long*>(&g_edges[e]);
        int cnt = min(32, end - base);
        int j = 0;
        for (; j + 8 <= cnt; j += 8) {
            float4 x[8];
            float  vv[8];
            #pragma unroll
            for (int u = 0; u < 8; ++u) {
                long long ej = __shfl_sync(0xffffffffu, ed, j + u);
                int cj = (int)ej;
                vv[u] = __int_as_float((int)(ej >> 32));
                const float4* p = (cj < split) ? (srcU + (long long)cj * 32)
                                               : (srcI + (long long)(cj - split) * 32);
                x[u] = __ldg(p + lane);
            }
            #pragma unroll
            for (int u = 0; u < 8; ++u) {
                acc.x = fmaf(vv[u], x[u].x, acc.x);
                acc.y = fmaf(vv[u], x[u].y, acc.y);
                acc.z = fmaf(vv[u], x[u].z, acc.z);
                acc.w = fmaf(vv[u], x[u].w, acc.w);
            }
        }
        for (; j < cnt; ++j) {
            long long ej = __shfl_sync(0xffffffffu, ed, j);
            int cj = (int)ej;
            float vj = __int_as_float((int)(ej >> 32));
            const float4* pj = (cj < split) ? (srcU + (long long)cj * 32)
                                            : (srcI + (long long)(cj - split) * 32);
            float4 x = __ldg(pj + lane);
            acc.x = fmaf(vj, x.x, acc.x);
            acc.y = fmaf(vj, x.y, acc.y);
            acc.z = fmaf(vj, x.z, acc.z);
            acc.w = fmaf(vj, x.w, acc.w);
        }
    }
    dst[w * 32 + lane] = acc;
}

// users/items may be int32 or int64 (JAX x64 ambiguity): detect on device.
__device__ __forceinline__ bool is_i64(const int* p) {
    bool z = true;
    #pragma unroll
    for (int j = 1; j < 64; j += 2) z = z && (p[j] == 0);
    return z;
}

// Gather + 0.25*add into out. which: 0 = raw inputs (split), 1 = g_Y, 2 = g_X.
__global__ void k_gather(const int* __restrict__ users, const int* __restrict__ items,
                         const float4* __restrict__ embU, const float4* __restrict__ embI,
                         int which, float4* __restrict__ out, int init) {
    int w = (blockIdx.x * blockDim.x + threadIdx.x) >> 5;
    int lane = threadIdx.x & 31;
    if (w >= 2 * BATCHQ) return;

    const float4* srcU;
    const float4* srcI;
    int split;
    if (which == 0) { srcU = embU; srcI = embI; split = U_COUNT; }
    else if (which == 1) {
        srcU = reinterpret_cast<const float4*>(g_Y); srcI = srcU; split = NN;
    } else {
        srcU = reinterpret_cast<const float4*>(g_X); srcI = srcU; split = NN;
    }

    int node;
    if (w < BATCHQ) {
        bool w64 = is_i64(users);
        node = w64 ? users[2 * w] : users[w];
    } else {
        int idx = w - BATCHQ;
        bool w64 = is_i64(items);
        node = U_COUNT + (w64 ? items[2 * idx] : items[idx]);
    }
    node = max(0, min(NN - 1, node));
    const float4* p = (node < split) ? (srcU + (long long)node * 32)
                                     : (srcI + (long long)(node - split) * 32);
    float4 v = p[lane];
    float4 o = init ? make_float4(0.f, 0.f, 0.f, 0.f) : out[w * 32 + lane];
    o.x += 0.25f * v.x;
    o.y += 0.25f * v.y;
    o.z += 0.25f * v.z;
    o.w += 0.25f * v.w;
    out[w * 32 + lane] = o;
}

extern "C" void kernel_launch(void* const* d_in, const int* in_sizes, int n_in,
                              void* d_out, int out_size) {
    const float4* user_emb = (const float4*)d_in[0];
    const float4* item_emb = (const float4*)d_in[1];
    const float*  adj_vals = (const float*)d_in[2];
    const int*    adj_rows = (const int*)d_in[3];
    const int*    adj_cols = (const int*)d_in[4];
    const int*    users    = (const int*)d_in[5];
    const int*    items    = (const int*)d_in[6];
    float4*       out      = (float4*)d_out;

    const int T = 256;

    // CSR build
    k_zero_counts<<<(N_PAD + T - 1) / T, T>>>();
    k_hist<<<(NNZ_C + T - 1) / T, T>>>(adj_rows);
    k_scan_part<<<NBLK_SCAN, 1024>>>();
    k_scan_add<<<NBLK_SCAN, 1024>>>();
    k_scatter<<<(NNZ_C + T - 1) / T, T>>>(adj_rows, adj_cols, adj_vals);

    const int GATHER_BLOCKS = (2 * BATCHQ * 32 + T - 1) / T;
    const int SPMM_BLOCKS   = (NN * 32 + T - 1) / T;

    // layer 0 (ego itself) — read raw inputs
    k_gather<<<GATHER_BLOCKS, T>>>(users, items, user_emb, item_emb, 0, out, 1);
    // layer 1: inputs -> Y
    k_spmm<<<SPMM_BLOCKS, T>>>(user_emb, item_emb, 0);
    k_gather<<<GATHER_BLOCKS, T>>>(users, items, user_emb, item_emb, 1, out, 0);
    // layer 2: Y -> X
    k_spmm<<<SPMM_BLOCKS, T>>>(user_emb, item_emb, 1);
    k_gather<<<GATHER_BLOCKS, T>>>(users, items, user_emb, item_emb, 2, out, 0);
    // layer 3: X -> Y
    k_spmm<<<SPMM_BLOCKS, T>>>(user_emb, item_emb, 2);
    k_gather<<<GATHER_BLOCKS, T>>>(users, items, user_emb, item_emb, 1, out, 0);
}

// round 6
// speedup vs baseline: 1.3683x; 1.3683x over previous
#include <cuda_runtime.h>
#include <cuda_fp16.h>

// ---------------------------------------------------------------------------
// GCNMixEncoder R6: fp16 intermediate storage to halve LTS traffic.
// - CSR build (hist -> 2-phase scan -> scatter, packed int2 edges)
// - one-time fp32->fp16 convert of embeddings (g_H0)
// - 3x warp-per-row SpMM, fp16 rows (256B), fp32 accumulate, x16 per-layer
//   scale to keep fp16 values in normal range
// - gathers: layer0 from fp32 inputs (exact), layers 1-3 from fp16 buffers
//   with weights 0.25/16^k
// ---------------------------------------------------------------------------

#define U_COUNT 100000
#define I_COUNT 50000
#define NN      (U_COUNT + I_COUNT)   // 150000
#define NNZ_C   1600000
#define BATCHQ  4096
#define SCAN_CHUNK 4096
#define N_PAD   151552                 // ceil(NN/4096)*4096
#define NBLK_SCAN (N_PAD / SCAN_CHUNK) // 37
#define LSCALE  16.0f

__device__ __half g_H0[(long long)NN * 128];
__device__ __half g_H1[(long long)NN * 128];
__device__ __half g_H2[(long long)NN * 128];
__device__ int   g_counts[N_PAD];
__device__ int   g_rowptr[NN + 1];
__device__ int   g_cursor[NN];
__device__ int   g_bsums[64];
__device__ int2  g_edges[NNZ_C];       // {col, float_as_int(val)}

__global__ void k_zero_counts() {
    int i = blockIdx.x * blockDim.x + threadIdx.x;
    if (i < N_PAD) g_counts[i] = 0;
}

// Convert fp32 inputs -> fp16 g_H0. One thread per float4 (4 elems).
__global__ void k_convert(const float4* __restrict__ ue, const float4* __restrict__ ie) {
    int i = blockIdx.x * blockDim.x + threadIdx.x;   // float4 index
    const int UQ = U_COUNT * 32;
    const int TQ = NN * 32;
    if (i >= TQ) return;
    float4 f = (i < UQ) ? __ldg(&ue[i]) : __ldg(&ie[i - UQ]);
    __half2 a = __floats2half2_rn(f.x, f.y);
    __half2 b = __floats2half2_rn(f.z, f.w);
    uint2 o;
    o.x = *reinterpret_cast<unsigned*>(&a);
    o.y = *reinterpret_cast<unsigned*>(&b);
    reinterpret_cast<uint2*>(g_H0)[i] = o;
}

__global__ void k_hist(const int* __restrict__ rows) {
    int e = blockIdx.x * blockDim.x + threadIdx.x;
    if (e < NNZ_C) atomicAdd(&g_counts[rows[e]], 1);
}

// Phase 1: block-local exclusive scan of a 4096-elem chunk; total to g_bsums.
__global__ void k_scan_part() {
    __shared__ int wsum[32];
    int b = blockIdx.x, t = threadIdx.x, lane = t & 31, wid = t >> 5;
    int i0 = b * SCAN_CHUNK + t * 4;
    int4 c = *reinterpret_cast<const int4*>(&g_counts[i0]);
    int p1 = c.x;
    int p2 = p1 + c.y;
    int p3 = p2 + c.z;
    int tot = p3 + c.w;
    int v = tot;
    #pragma unroll
    for (int o = 1; o < 32; o <<= 1) {
        int n = __shfl_up_sync(0xffffffffu, v, o);
        if (lane >= o) v += n;
    }
    if (lane == 31) wsum[wid] = v;
    __syncthreads();
    if (wid == 0) {
        int wv = wsum[lane];
        #pragma unroll
        for (int o = 1; o < 32; o <<= 1) {
            int n = __shfl_up_sync(0xffffffffu, wv, o);
            if (lane >= o) wv += n;
        }
        wsum[lane] = wv;
    }
    __syncthreads();
    int warp_off = wid ? wsum[wid - 1] : 0;
    int excl = warp_off + (v - tot);
    if (i0     < NN) g_rowptr[i0]     = excl;
    if (i0 + 1 < NN) g_rowptr[i0 + 1] = excl + p1;
    if (i0 + 2 < NN) g_rowptr[i0 + 2] = excl + p2;
    if (i0 + 3 < NN) g_rowptr[i0 + 3] = excl + p3;
    if (t == 0) g_bsums[b] = wsum[31];
}

// Phase 2: add inter-block offsets + init cursor.
__global__ void k_scan_add() {
    __shared__ int s_off;
    int b = blockIdx.x, t = threadIdx.x;
    if (t == 0) {
        int s = 0;
        for (int j = 0; j < b; ++j) s += g_bsums[j];
        s_off = s;
    }
    __syncthreads();
    int off = s_off;
    int i0 = b * SCAN_CHUNK + t * 4;
    #pragma unroll
    for (int k = 0; k < 4; ++k) {
        int i = i0 + k;
        if (i < NN) {
            int r = g_rowptr[i] + off;
            g_rowptr[i] = r;
            g_cursor[i] = r;
        }
    }
    if (b == 0 && t == 0) g_rowptr[NN] = NNZ_C;
}

__global__ void k_scatter(const int* __restrict__ rows, const int* __restrict__ cols,
                          const float* __restrict__ vals) {
    int e = blockIdx.x * blockDim.x + threadIdx.x;
    if (e >= NNZ_C) return;
    int r = rows[e];
    int p = atomicAdd(&g_cursor[r], 1);
    g_edges[p] = make_int2(cols[e], __float_as_int(vals[e]));
}

// ---------------------------------------------------------------------------
// Warp-per-row CSR SpMM over fp16 rows (256B = 32 lanes x 8B).
// fp32 accumulate; store acc * LSCALE as fp16.
//   mode 0: g_H0 -> g_H1 ; mode 1: g_H1 -> g_H2 ; mode 2: g_H2 -> g_H1
// ---------------------------------------------------------------------------
__global__ void k_spmm_h(int mode) {
    int w = (blockIdx.x * blockDim.x + threadIdx.x) >> 5;
    int lane = threadIdx.x & 31;
    if (w >= NN) return;

    const uint2* src;
    uint2* dst;
    if (mode == 0)      { src = reinterpret_cast<const uint2*>(g_H0);
                          dst = reinterpret_cast<uint2*>(g_H1); }
    else if (mode == 1) { src = reinterpret_cast<const uint2*>(g_H1);
                          dst = reinterpret_cast<uint2*>(g_H2); }
    else                { src = reinterpret_cast<const uint2*>(g_H2);
                          dst = reinterpret_cast<uint2*>(g_H1); }

    int start = g_rowptr[w], end = g_rowptr[w + 1];
    float ax = 0.f, ay = 0.f, az = 0.f, aw = 0.f;
    for (int base = start; base < end; base += 32) {
        int e = base + lane;
        long long ed = 0;
        if (e < end) ed = *reinterpret_cast<const long long*>(&g_edges[e]);
        int cnt = min(32, end - base);
        int j = 0;
        for (; j + 4 <= cnt; j += 4) {
            uint2 r[4];
            float vv[4];
            #pragma unroll
            for (int u = 0; u < 4; ++u) {
                long long ej = __shfl_sync(0xffffffffu, ed, j + u);
                int cj = (int)ej;
                vv[u] = __int_as_float((int)(ej >> 32));
                r[u] = __ldg(&src[(long long)cj * 32 + lane]);
            }
            #pragma unroll
            for (int u = 0; u < 4; ++u) {
                __half2 h0 = *reinterpret_cast<__half2*>(&r[u].x);
                __half2 h1 = *reinterpret_cast<__half2*>(&r[u].y);
                float2 f0 = __half22float2(h0);
                float2 f1 = __half22float2(h1);
                ax = fmaf(vv[u], f0.x, ax);
                ay = fmaf(vv[u], f0.y, ay);
                az = fmaf(vv[u], f1.x, az);
                aw = fmaf(vv[u], f1.y, aw);
            }
        }
        for (; j < cnt; ++j) {
            long long ej = __shfl_sync(0xffffffffu, ed, j);
            int cj = (int)ej;
            float vj = __int_as_float((int)(ej >> 32));
            uint2 rr = __ldg(&src[(long long)cj * 32 + lane]);
            __half2 h0 = *reinterpret_cast<__half2*>(&rr.x);
            __half2 h1 = *reinterpret_cast<__half2*>(&rr.y);
            float2 f0 = __half22float2(h0);
            float2 f1 = __half22float2(h1);
            ax = fmaf(vj, f0.x, ax);
            ay = fmaf(vj, f0.y, ay);
            az = fmaf(vj, f1.x, az);
            aw = fmaf(vj, f1.y, aw);
        }
    }
    __half2 o0 = __floats2half2_rn(ax * LSCALE, ay * LSCALE);
    __half2 o1 = __floats2half2_rn(az * LSCALE, aw * LSCALE);
    uint2 o;
    o.x = *reinterpret_cast<unsigned*>(&o0);
    o.y = *reinterpret_cast<unsigned*>(&o1);
    dst[(long long)w * 32 + lane] = o;
}

// users/items may be int32 or int64 (JAX x64 ambiguity): detect on device.
__device__ __forceinline__ bool is_i64(const int* p) {
    bool z = true;
    #pragma unroll
    for (int j = 1; j < 64; j += 2) z = z && (p[j] == 0);
    return z;
}

__device__ __forceinline__ int q_node(const int* __restrict__ users,
                                      const int* __restrict__ items, int w) {
    int node;
    if (w < BATCHQ) {
        bool w64 = is_i64(users);
        node = w64 ? users[2 * w] : users[w];
    } else {
        int idx = w - BATCHQ;
        bool w64 = is_i64(items);
        node = U_COUNT + (w64 ? items[2 * idx] : items[idx]);
    }
    return max(0, min(NN - 1, node));
}

// Layer-0 gather from exact fp32 inputs (split), weight 0.25, init out.
__global__ void k_gather0(const int* __restrict__ users, const int* __restrict__ items,
                          const float4* __restrict__ embU, const float4* __restrict__ embI,
                          float4* __restrict__ out) {
    int w = (blockIdx.x * blockDim.x + threadIdx.x) >> 5;
    int lane = threadIdx.x & 31;
    if (w >= 2 * BATCHQ) return;
    int node = q_node(users, items, w);
    const float4* p = (node < U_COUNT) ? (embU + (long long)node * 32)
                                       : (embI + (long long)(node - U_COUNT) * 32);
    float4 v = p[lane];
    out[w * 32 + lane] = make_float4(0.25f * v.x, 0.25f * v.y, 0.25f * v.z, 0.25f * v.w);
}

// fp16 gather + weighted add. sel: 1 = g_H1, 2 = g_H2.
__global__ void k_gatherh(const int* __restrict__ users, const int* __restrict__ items,
                          int sel, float wt, float4* __restrict__ out) {
    int w = (blockIdx.x * blockDim.x + threadIdx.x) >> 5;
    int lane = threadIdx.x & 31;
    if (w >= 2 * BATCHQ) return;
    int node = q_node(users, items, w);
    const uint2* src = (sel == 1) ? reinterpret_cast<const uint2*>(g_H1)
                                  : reinterpret_cast<const uint2*>(g_H2);
    uint2 rr = src[(long long)node * 32 + lane];
    __half2 h0 = *reinterpret_cast<__half2*>(&rr.x);
    __half2 h1 = *reinterpret_cast<__half2*>(&rr.y);
    float2 f0 = __half22float2(h0);
    float2 f1 = __half22float2(h1);
    float4 o = out[w * 32 + lane];
    o.x = fmaf(wt, f0.x, o.x);
    o.y = fmaf(wt, f0.y, o.y);
    o.z = fmaf(wt, f1.x, o.z);
    o.w = fmaf(wt, f1.y, o.w);
    out[w * 32 + lane] = o;
}

extern "C" void kernel_launch(void* const* d_in, const int* in_sizes, int n_in,
                              void* d_out, int out_size) {
    const float4* user_emb = (const float4*)d_in[0];
    const float4* item_emb = (const float4*)d_in[1];
    const float*  adj_vals = (const float*)d_in[2];
    const int*    adj_rows = (const int*)d_in[3];
    const int*    adj_cols = (const int*)d_in[4];
    const int*    users    = (const int*)d_in[5];
    const int*    items    = (const int*)d_in[6];
    float4*       out      = (float4*)d_out;

    const int T = 256;

    // CSR build + fp16 convert
    k_zero_counts<<<(N_PAD + T - 1) / T, T>>>();
    k_convert<<<(NN * 32 + T - 1) / T, T>>>(user_emb, item_emb);
    k_hist<<<(NNZ_C + T - 1) / T, T>>>(adj_rows);
    k_scan_part<<<NBLK_SCAN, 1024>>>();
    k_scan_add<<<NBLK_SCAN, 1024>>>();
    k_scatter<<<(NNZ_C + T - 1) / T, T>>>(adj_rows, adj_cols, adj_vals);

    const int GATHER_BLOCKS = (2 * BATCHQ * 32 + T - 1) / T;
    const int SPMM_BLOCKS   = (NN * 32 + T - 1) / T;

    // layer 0 (ego) — exact fp32 inputs
    k_gather0<<<GATHER_BLOCKS, T>>>(users, items, user_emb, item_emb, out);
    // layer 1: H0 -> H1 (stored x16)
    k_spmm_h<<<SPMM_BLOCKS, T>>>(0);
    k_gatherh<<<GATHER_BLOCKS, T>>>(users, items, 1, 0.25f / 16.0f, out);
    // layer 2: H1 -> H2 (stored x256)
    k_spmm_h<<<SPMM_BLOCKS, T>>>(1);
    k_gatherh<<<GATHER_BLOCKS, T>>>(users, items, 2, 0.25f / 256.0f, out);
    // layer 3: H2 -> H1 (stored x4096)
    k_spmm_h<<<SPMM_BLOCKS, T>>>(2);
    k_gatherh<<<GATHER_BLOCKS, T>>>(users, items, 1, 0.25f / 4096.0f, out);
}

// round 7
// speedup vs baseline: 1.6138x; 1.1795x over previous
#include <cuda_runtime.h>
#include <cuda_fp16.h>

// ---------------------------------------------------------------------------
// GCNMixEncoder R7: fp16 intermediates (R6) + demand-driven propagation.
// Only the 8192 query nodes are read from layer-3; only Q u N(Q) from
// layer-2. Layer-3 SpMM runs on ~8K rows, layer-2 on ~70K, layer-1 full.
// ---------------------------------------------------------------------------

#define U_COUNT 100000
#define I_COUNT 50000
#define NN      (U_COUNT + I_COUNT)   // 150000
#define NNZ_C   1600000
#define BATCHQ  4096
#define SCAN_CHUNK 4096
#define N_PAD   151552                 // ceil(NN/4096)*4096
#define NBLK_SCAN (N_PAD / SCAN_CHUNK) // 37
#define LSCALE  16.0f

__device__ __half g_H0[(long long)NN * 128];
__device__ __half g_H1[(long long)NN * 128];
__device__ __half g_H2[(long long)NN * 128];
__device__ __half g_H3[(long long)NN * 128];
__device__ int   g_counts[N_PAD];
__device__ int   g_rowptr[NN + 1];
__device__ int   g_cursor[NN];
__device__ int   g_bsums[64];
__device__ int2  g_edges[NNZ_C];       // {col, float_as_int(val)}
__device__ int   g_flag[N_PAD];        // layer-2 active-row flags
__device__ int   g_list2[NN];          // compacted active rows
__device__ int   g_m2;                 // active count

__global__ void k_zero_counts() {
    int i = blockIdx.x * blockDim.x + threadIdx.x;
    if (i < N_PAD) { g_counts[i] = 0; g_flag[i] = 0; }
    if (i == 0) g_m2 = 0;
}

// Convert fp32 inputs -> fp16 g_H0. One thread per float4 (4 elems).
__global__ void k_convert(const float4* __restrict__ ue, const float4* __restrict__ ie) {
    int i = blockIdx.x * blockDim.x + threadIdx.x;   // float4 index
    const int UQ = U_COUNT * 32;
    const int TQ = NN * 32;
    if (i >= TQ) return;
    float4 f = (i < UQ) ? __ldg(&ue[i]) : __ldg(&ie[i - UQ]);
    __half2 a = __floats2half2_rn(f.x, f.y);
    __half2 b = __floats2half2_rn(f.z, f.w);
    uint2 o;
    o.x = *reinterpret_cast<unsigned*>(&a);
    o.y = *reinterpret_cast<unsigned*>(&b);
    reinterpret_cast<uint2*>(g_H0)[i] = o;
}

__global__ void k_hist(const int* __restrict__ rows) {
    int e = blockIdx.x * blockDim.x + threadIdx.x;
    if (e < NNZ_C) atomicAdd(&g_counts[rows[e]], 1);
}

// Phase 1: block-local exclusive scan of a 4096-elem chunk; total to g_bsums.
__global__ void k_scan_part() {
    __shared__ int wsum[32];
    int b = blockIdx.x, t = threadIdx.x, lane = t & 31, wid = t >> 5;
    int i0 = b * SCAN_CHUNK + t * 4;
    int4 c = *reinterpret_cast<const int4*>(&g_counts[i0]);
    int p1 = c.x;
    int p2 = p1 + c.y;
    int p3 = p2 + c.z;
    int tot = p3 + c.w;
    int v = tot;
    #pragma unroll
    for (int o = 1; o < 32; o <<= 1) {
        int n = __shfl_up_sync(0xffffffffu, v, o);
        if (lane >= o) v += n;
    }
    if (lane == 31) wsum[wid] = v;
    __syncthreads();
    if (wid == 0) {
        int wv = wsum[lane];
        #pragma unroll
        for (int o = 1; o < 32; o <<= 1) {
            int n = __shfl_up_sync(0xffffffffu, wv, o);
            if (lane >= o) wv += n;
        }
        wsum[lane] = wv;
    }
    __syncthreads();
    int warp_off = wid ? wsum[wid - 1] : 0;
    int excl = warp_off + (v - tot);
    if (i0     < NN) g_rowptr[i0]     = excl;
    if (i0 + 1 < NN) g_rowptr[i0 + 1] = excl + p1;
    if (i0 + 2 < NN) g_rowptr[i0 + 2] = excl + p2;
    if (i0 + 3 < NN) g_rowptr[i0 + 3] = excl + p3;
    if (t == 0) g_bsums[b] = wsum[31];
}

// Phase 2: add inter-block offsets + init cursor.
__global__ void k_scan_add() {
    __shared__ int s_off;
    int b = blockIdx.x, t = threadIdx.x;
    if (t == 0) {
        int s = 0;
        for (int j = 0; j < b; ++j) s += g_bsums[j];
        s_off = s;
    }
    __syncthreads();
    int off = s_off;
    int i0 = b * SCAN_CHUNK + t * 4;
    #pragma unroll
    for (int k = 0; k < 4; ++k) {
        int i = i0 + k;
        if (i < NN) {
            int r = g_rowptr[i] + off;
            g_rowptr[i] = r;
            g_cursor[i] = r;
        }
    }
    if (b == 0 && t == 0) g_rowptr[NN] = NNZ_C;
}

__global__ void k_scatter(const int* __restrict__ rows, const int* __restrict__ cols,
                          const float* __restrict__ vals) {
    int e = blockIdx.x * blockDim.x + threadIdx.x;
    if (e >= NNZ_C) return;
    int r = rows[e];
    int p = atomicAdd(&g_cursor[r], 1);
    g_edges[p] = make_int2(cols[e], __float_as_int(vals[e]));
}

// users/items may be int32 or int64 (JAX x64 ambiguity): detect on device.
__device__ __forceinline__ bool is_i64(const int* p) {
    bool z = true;
    #pragma unroll
    for (int j = 1; j < 64; j += 2) z = z && (p[j] == 0);
    return z;
}

__device__ __forceinline__ int q_node(const int* __restrict__ users,
                                      const int* __restrict__ items, int w) {
    int node;
    if (w < BATCHQ) {
        bool w64 = is_i64(users);
        node = w64 ? users[2 * w] : users[w];
    } else {
        int idx = w - BATCHQ;
        bool w64 = is_i64(items);
        node = U_COUNT + (w64 ? items[2 * idx] : items[idx]);
    }
    return max(0, min(NN - 1, node));
}

// Flag Q and N(Q): one warp per query node walks its CSR row.
__global__ void k_expand(const int* __restrict__ users, const int* __restrict__ items) {
    int w = (blockIdx.x * blockDim.x + threadIdx.x) >> 5;
    int lane = threadIdx.x & 31;
    if (w >= 2 * BATCHQ) return;
    int node = q_node(users, items, w);
    if (lane == 0) g_flag[node] = 1;
    int s = g_rowptr[node], e = g_rowptr[node + 1];
    for (int i = s + lane; i < e; i += 32)
        g_flag[g_edges[i].x] = 1;            // races benign (all write 1)
}

// Warp-aggregated compaction of g_flag -> g_list2 / g_m2.
__global__ void k_compact() {
    int i = blockIdx.x * blockDim.x + threadIdx.x;
    int lane = threadIdx.x & 31;
    int f = (i < NN) ? g_flag[i] : 0;
    unsigned m = __ballot_sync(0xffffffffu, f);
    int cnt = __popc(m);
    int pos = 0;
    if (lane == 0 && cnt) pos = atomicAdd(&g_m2, cnt);
    pos = __shfl_sync(0xffffffffu, pos, 0);
    if (f) g_list2[pos + __popc(m & ((1u << lane) - 1))] = i;
}

// ---------------------------------------------------------------------------
// Shared SpMM row body over fp16 rows (256B), fp32 accumulate, store *LSCALE.
// ---------------------------------------------------------------------------
__device__ __forceinline__ void spmm_row(int row, int lane,
                                         const uint2* __restrict__ src,
                                         uint2* __restrict__ dst) {
    int start = g_rowptr[row], end = g_rowptr[row + 1];
    float ax = 0.f, ay = 0.f, az = 0.f, aw = 0.f;
    for (int base = start; base < end; base += 32) {
        int e = base + lane;
        long long ed = 0;
        if (e < end) ed = *reinterpret_cast<const long long*>(&g_edges[e]);
        int cnt = min(32, end - base);
        int j = 0;
        for (; j + 4 <= cnt; j += 4) {
            uint2 r[4];
            float vv[4];
            #pragma unroll
            for (int u = 0; u < 4; ++u) {
                long long ej = __shfl_sync(0xffffffffu, ed, j + u);
                int cj = (int)ej;
                vv[u] = __int_as_float((int)(ej >> 32));
                r[u] = __ldg(&src[(long long)cj * 32 + lane]);
            }
            #pragma unroll
            for (int u = 0; u < 4; ++u) {
                __half2 h0 = *reinterpret_cast<__half2*>(&r[u].x);
                __half2 h1 = *reinterpret_cast<__half2*>(&r[u].y);
                float2 f0 = __half22float2(h0);
                float2 f1 = __half22float2(h1);
                ax = fmaf(vv[u], f0.x, ax);
                ay = fmaf(vv[u], f0.y, ay);
                az = fmaf(vv[u], f1.x, az);
                aw = fmaf(vv[u], f1.y, aw);
            }
        }
        for (; j < cnt; ++j) {
            long long ej = __shfl_sync(0xffffffffu, ed, j);
            int cj = (int)ej;
            float vj = __int_as_float((int)(ej >> 32));
            uint2 rr = __ldg(&src[(long long)cj * 32 + lane]);
            __half2 h0 = *reinterpret_cast<__half2*>(&rr.x);
            __half2 h1 = *reinterpret_cast<__half2*>(&rr.y);
            float2 f0 = __half22float2(h0);
            float2 f1 = __half22float2(h1);
            ax = fmaf(vj, f0.x, ax);
            ay = fmaf(vj, f0.y, ay);
            az = fmaf(vj, f1.x, az);
            aw = fmaf(vj, f1.y, aw);
        }
    }
    __half2 o0 = __floats2half2_rn(ax * LSCALE, ay * LSCALE);
    __half2 o1 = __floats2half2_rn(az * LSCALE, aw * LSCALE);
    uint2 o;
    o.x = *reinterpret_cast<unsigned*>(&o0);
    o.y = *reinterpret_cast<unsigned*>(&o1);
    dst[(long long)row * 32 + lane] = o;
}

// Layer 1: all rows, H0 -> H1.
__global__ void k_spmm_full() {
    int w = (blockIdx.x * blockDim.x + threadIdx.x) >> 5;
    int lane = threadIdx.x & 31;
    if (w >= NN) return;
    spmm_row(w, lane, reinterpret_cast<const uint2*>(g_H0),
             reinterpret_cast<uint2*>(g_H1));
}

// Layer 2: active rows from g_list2, H1 -> H2.
__global__ void k_spmm_act() {
    int w = (blockIdx.x * blockDim.x + threadIdx.x) >> 5;
    int lane = threadIdx.x & 31;
    if (w >= g_m2) return;
    int row = g_list2[w];
    spmm_row(row, lane, reinterpret_cast<const uint2*>(g_H1),
             reinterpret_cast<uint2*>(g_H2));
}

// Layer 3: query rows only (dupes benign), H2 -> H3.
__global__ void k_spmm_q(const int* __restrict__ users, const int* __restrict__ items) {
    int w = (blockIdx.x * blockDim.x + threadIdx.x) >> 5;
    int lane = threadIdx.x & 31;
    if (w >= 2 * BATCHQ) return;
    int row = q_node(users, items, w);
    spmm_row(row, lane, reinterpret_cast<const uint2*>(g_H2),
             reinterpret_cast<uint2*>(g_H3));
}

// Layer-0 gather from exact fp32 inputs (split), weight 0.25, init out.
__global__ void k_gather0(const int* __restrict__ users, const int* __restrict__ items,
                          const float4* __restrict__ embU, const float4* __restrict__ embI,
                          float4* __restrict__ out) {
    int w = (blockIdx.x * blockDim.x + threadIdx.x) >> 5;
    int lane = threadIdx.x & 31;
    if (w >= 2 * BATCHQ) return;
    int node = q_node(users, items, w);
    const float4* p = (node < U_COUNT) ? (embU + (long long)node * 32)
                                       : (embI + (long long)(node - U_COUNT) * 32);
    float4 v = p[lane];
    out[w * 32 + lane] = make_float4(0.25f * v.x, 0.25f * v.y, 0.25f * v.z, 0.25f * v.w);
}

// fp16 gather + weighted add. sel: 1 = g_H1, 2 = g_H2, 3 = g_H3.
__global__ void k_gatherh(const int* __restrict__ users, const int* __restrict__ items,
                          int sel, float wt, float4* __restrict__ out) {
    int w = (blockIdx.x * blockDim.x + threadIdx.x) >> 5;
    int lane = threadIdx.x & 31;
    if (w >= 2 * BATCHQ) return;
    int node = q_node(users, items, w);
    const uint2* src = (sel == 1) ? reinterpret_cast<const uint2*>(g_H1)
                     : (sel == 2) ? reinterpret_cast<const uint2*>(g_H2)
                                  : reinterpret_cast<const uint2*>(g_H3);
    uint2 rr = src[(long long)node * 32 + lane];
    __half2 h0 = *reinterpret_cast<__half2*>(&rr.x);
    __half2 h1 = *reinterpret_cast<__half2*>(&rr.y);
    float2 f0 = __half22float2(h0);
    float2 f1 = __half22float2(h1);
    float4 o = out[w * 32 + lane];
    o.x = fmaf(wt, f0.x, o.x);
    o.y = fmaf(wt, f0.y, o.y);
    o.z = fmaf(wt, f1.x, o.z);
    o.w = fmaf(wt, f1.y, o.w);
    out[w * 32 + lane] = o;
}

extern "C" void kernel_launch(void* const* d_in, const int* in_sizes, int n_in,
                              void* d_out, int out_size) {
    const float4* user_emb = (const float4*)d_in[0];
    const float4* item_emb = (const float4*)d_in[1];
    const float*  adj_vals = (const float*)d_in[2];
    const int*    adj_rows = (const int*)d_in[3];
    const int*    adj_cols = (const int*)d_in[4];
    const int*    users    = (const int*)d_in[5];
    const int*    items    = (const int*)d_in[6];
    float4*       out      = (float4*)d_out;

    const int T = 256;
    const int GATHER_BLOCKS = (2 * BATCHQ * 32 + T - 1) / T;
    const int SPMM_BLOCKS   = (NN * 32 + T - 1) / T;

    // CSR build + fp16 convert
    k_zero_counts<<<(N_PAD + T - 1) / T, T>>>();
    k_convert<<<(NN * 32 + T - 1) / T, T>>>(user_emb, item_emb);
    k_hist<<<(NNZ_C + T - 1) / T, T>>>(adj_rows);
    k_scan_part<<<NBLK_SCAN, 1024>>>();
    k_scan_add<<<NBLK_SCAN, 1024>>>();
    k_scatter<<<(NNZ_C + T - 1) / T, T>>>(adj_rows, adj_cols, adj_vals);

    // Active-set construction (needs CSR)
    k_expand<<<GATHER_BLOCKS, T>>>(users, items);
    k_compact<<<(N_PAD + T - 1) / T, T>>>();

    // layer 0 (ego) — exact fp32 inputs
    k_gather0<<<GATHER_BLOCKS, T>>>(users, items, user_emb, item_emb, out);
    // layer 1: H0 -> H1 (all rows, stored x16)
    k_spmm_full<<<SPMM_BLOCKS, T>>>();
    k_gatherh<<<GATHER_BLOCKS, T>>>(users, items, 1, 0.25f / 16.0f, out);
    // layer 2: H1 -> H2 (active rows only, stored x256)
    k_spmm_act<<<SPMM_BLOCKS, T>>>();
    k_gatherh<<<GATHER_BLOCKS, T>>>(users, items, 2, 0.25f / 256.0f, out);
    // layer 3: H2 -> H3 (query rows only, stored x4096)
    k_spmm_q<<<GATHER_BLOCKS, T>>>(users, items);
    k_gatherh<<<GATHER_BLOCKS, T>>>(users, items, 3, 0.25f / 4096.0f, out);
}

// round 8
// speedup vs baseline: 2.2143x; 1.3721x over previous
#include <cuda_runtime.h>
#include <cuda_fp16.h>

// ---------------------------------------------------------------------------
// GCNMixEncoder R8: fp16 intermediates + demand-driven propagation (R7)
//  + fused final kernel (layer-3 SpMM + all gathers, single out write)
//  + atomic-free scatter (hist records within-row position)
//  + x16 layer scale folded into edge values.
// ---------------------------------------------------------------------------

#define U_COUNT 100000
#define I_COUNT 50000
#define NN      (U_COUNT + I_COUNT)   // 150000
#define NNZ_C   1600000
#define BATCHQ  4096
#define SCAN_CHUNK 4096
#define N_PAD   151552                 // ceil(NN/4096)*4096
#define NBLK_SCAN (N_PAD / SCAN_CHUNK) // 37

__device__ __half g_H0[(long long)NN * 128];
__device__ __half g_H1[(long long)NN * 128];
__device__ __half g_H2[(long long)NN * 128];
__device__ int   g_counts[N_PAD];
__device__ int   g_rowptr[NN + 1];
__device__ int   g_bsums[64];
__device__ int   g_lpos[NNZ_C];        // within-row position from hist
__device__ int2  g_edges[NNZ_C];       // {col, float_as_int(16*val)}
__device__ int   g_flag[N_PAD];        // layer-2 active-row flags
__device__ int   g_list2[NN];          // compacted active rows
__device__ int   g_m2;                 // active count

__global__ void k_zero() {
    int i = blockIdx.x * blockDim.x + threadIdx.x;
    if (i < N_PAD) { g_counts[i] = 0; g_flag[i] = 0; }
    if (i == 0) g_m2 = 0;
}

// Convert fp32 inputs -> fp16 g_H0. One thread per float4 (4 elems).
__global__ void k_convert(const float4* __restrict__ ue, const float4* __restrict__ ie) {
    int i = blockIdx.x * blockDim.x + threadIdx.x;   // float4 index
    const int UQ = U_COUNT * 32;
    const int TQ = NN * 32;
    if (i >= TQ) return;
    float4 f = (i < UQ) ? __ldg(&ue[i]) : __ldg(&ie[i - UQ]);
    __half2 a = __floats2half2_rn(f.x, f.y);
    __half2 b = __floats2half2_rn(f.z, f.w);
    uint2 o;
    o.x = *reinterpret_cast<unsigned*>(&a);
    o.y = *reinterpret_cast<unsigned*>(&b);
    reinterpret_cast<uint2*>(g_H0)[i] = o;
}

// Histogram; atomicAdd's return value is this edge's within-row slot.
__global__ void k_hist(const int* __restrict__ rows) {
    int e = blockIdx.x * blockDim.x + threadIdx.x;
    if (e >= NNZ_C) return;
    g_lpos[e] = atomicAdd(&g_counts[rows[e]], 1);
}

// Phase 1: block-local exclusive scan of a 4096-elem chunk; total to g_bsums.
__global__ void k_scan_part() {
    __shared__ int wsum[32];
    int b = blockIdx.x, t = threadIdx.x, lane = t & 31, wid = t >> 5;
    int i0 = b * SCAN_CHUNK + t * 4;
    int4 c = *reinterpret_cast<const int4*>(&g_counts[i0]);
    int p1 = c.x;
    int p2 = p1 + c.y;
    int p3 = p2 + c.z;
    int tot = p3 + c.w;
    int v = tot;
    #pragma unroll
    for (int o = 1; o < 32; o <<= 1) {
        int n = __shfl_up_sync(0xffffffffu, v, o);
        if (lane >= o) v += n;
    }
    if (lane == 31) wsum[wid] = v;
    __syncthreads();
    if (wid == 0) {
        int wv = wsum[lane];
        #pragma unroll
        for (int o = 1; o < 32; o <<= 1) {
            int n = __shfl_up_sync(0xffffffffu, wv, o);
            if (lane >= o) wv += n;
        }
        wsum[lane] = wv;
    }
    __syncthreads();
    int warp_off = wid ? wsum[wid - 1] : 0;
    int excl = warp_off + (v - tot);
    if (i0     < NN) g_rowptr[i0]     = excl;
    if (i0 + 1 < NN) g_rowptr[i0 + 1] = excl + p1;
    if (i0 + 2 < NN) g_rowptr[i0 + 2] = excl + p2;
    if (i0 + 3 < NN) g_rowptr[i0 + 3] = excl + p3;
    if (t == 0) g_bsums[b] = wsum[31];
}

// Phase 2: add inter-block offsets.
__global__ void k_scan_add() {
    __shared__ int s_off;
    int b = blockIdx.x, t = threadIdx.x;
    if (t == 0) {
        int s = 0;
        for (int j = 0; j < b; ++j) s += g_bsums[j];
        s_off = s;
    }
    __syncthreads();
    int off = s_off;
    int i0 = b * SCAN_CHUNK + t * 4;
    #pragma unroll
    for (int k = 0; k < 4; ++k) {
        int i = i0 + k;
        if (i < NN) g_rowptr[i] += off;
    }
    if (b == 0 && t == 0) g_rowptr[NN] = NNZ_C;
}

// Atomic-free scatter: final slot = rowptr[r] + lpos[e]. Edge val scaled x16.
__global__ void k_scatter(const int* __restrict__ rows, const int* __restrict__ cols,
                          const float* __restrict__ vals) {
    int e = blockIdx.x * blockDim.x + threadIdx.x;
    if (e >= NNZ_C) return;
    int r = rows[e];
    int p = g_rowptr[r] + g_lpos[e];
    g_edges[p] = make_int2(cols[e], __float_as_int(16.0f * vals[e]));
}

// users/items may be int32 or int64 (JAX x64 ambiguity): detect on device.
__device__ __forceinline__ bool is_i64(const int* p) {
    bool z = true;
    #pragma unroll
    for (int j = 1; j < 64; j += 2) z = z && (p[j] == 0);
    return z;
}

__device__ __forceinline__ int q_node(const int* __restrict__ users,
                                      const int* __restrict__ items, int w) {
    int node;
    if (w < BATCHQ) {
        bool w64 = is_i64(users);
        node = w64 ? users[2 * w] : users[w];
    } else {
        int idx = w - BATCHQ;
        bool w64 = is_i64(items);
        node = U_COUNT + (w64 ? items[2 * idx] : items[idx]);
    }
    return max(0, min(NN - 1, node));
}

// Flag Q and N(Q): one warp per query node walks its CSR row.
__global__ void k_expand(const int* __restrict__ users, const int* __restrict__ items) {
    int w = (blockIdx.x * blockDim.x + threadIdx.x) >> 5;
    int lane = threadIdx.x & 31;
    if (w >= 2 * BATCHQ) return;
    int node = q_node(users, items, w);
    if (lane == 0) g_flag[node] = 1;
    int s = g_rowptr[node], e = g_rowptr[node + 1];
    for (int i = s + lane; i < e; i += 32)
        g_flag[g_edges[i].x] = 1;            // races benign (all write 1)
}

// Warp-aggregated compaction of g_flag -> g_list2 / g_m2.
__global__ void k_compact() {
    int i = blockIdx.x * blockDim.x + threadIdx.x;
    int lane = threadIdx.x & 31;
    int f = (i < NN) ? g_flag[i] : 0;
    unsigned m = __ballot_sync(0xffffffffu, f);
    int cnt = __popc(m);
    int pos = 0;
    if (lane == 0 && cnt) pos = atomicAdd(&g_m2, cnt);
    pos = __shfl_sync(0xffffffffu, pos, 0);
    if (f) g_list2[pos + __popc(m & ((1u << lane) - 1))] = i;
}

// ---------------------------------------------------------------------------
// SpMM row accumulate over fp16 rows (256B), fp32 accumulate.
// (Edge values carry the x16 scale.)
// ---------------------------------------------------------------------------
__device__ __forceinline__ void spmm_acc(int row, int lane,
                                         const uint2* __restrict__ src,
                                         float& ax, float& ay, float& az, float& aw) {
    int start = g_rowptr[row], end = g_rowptr[row + 1];
    for (int base = start; base < end; base += 32) {
        int e = base + lane;
        long long ed = 0;
        if (e < end) ed = *reinterpret_cast<const long long*>(&g_edges[e]);
        int cnt = min(32, end - base);
        int j = 0;
        for (; j + 4 <= cnt; j += 4) {
            uint2 r[4];
            float vv[4];
            #pragma unroll
            for (int u = 0; u < 4; ++u) {
                long long ej = __shfl_sync(0xffffffffu, ed, j + u);
                int cj = (int)ej;
                vv[u] = __int_as_float((int)(ej >> 32));
                r[u] = __ldg(&src[(long long)cj * 32 + lane]);
            }
            #pragma unroll
            for (int u = 0; u < 4; ++u) {
                __half2 h0 = *reinterpret_cast<__half2*>(&r[u].x);
                __half2 h1 = *reinterpret_cast<__half2*>(&r[u].y);
                float2 f0 = __half22float2(h0);
                float2 f1 = __half22float2(h1);
                ax = fmaf(vv[u], f0.x, ax);
                ay = fmaf(vv[u], f0.y, ay);
                az = fmaf(vv[u], f1.x, az);
                aw = fmaf(vv[u], f1.y, aw);
            }
        }
        for (; j < cnt; ++j) {
            long long ej = __shfl_sync(0xffffffffu, ed, j);
            int cj = (int)ej;
            float vj = __int_as_float((int)(ej >> 32));
            uint2 rr = __ldg(&src[(long long)cj * 32 + lane]);
            __half2 h0 = *reinterpret_cast<__half2*>(&rr.x);
            __half2 h1 = *reinterpret_cast<__half2*>(&rr.y);
            float2 f0 = __half22float2(h0);
            float2 f1 = __half22float2(h1);
            ax = fmaf(vj, f0.x, ax);
            ay = fmaf(vj, f0.y, ay);
            az = fmaf(vj, f1.x, az);
            aw = fmaf(vj, f1.y, aw);
        }
    }
}

__device__ __forceinline__ void store_h(uint2* __restrict__ dst, int row, int lane,
                                        float ax, float ay, float az, float aw) {
    __half2 o0 = __floats2half2_rn(ax, ay);
    __half2 o1 = __floats2half2_rn(az, aw);
    uint2 o;
    o.x = *reinterpret_cast<unsigned*>(&o0);
    o.y = *reinterpret_cast<unsigned*>(&o1);
    dst[(long long)row * 32 + lane] = o;
}

// Layer 1: all rows, H0 -> H1 (stores 16*A*H0).
__global__ void k_spmm_full() {
    int w = (blockIdx.x * blockDim.x + threadIdx.x) >> 5;
    int lane = threadIdx.x & 31;
    if (w >= NN) return;
    float ax = 0.f, ay = 0.f, az = 0.f, aw = 0.f;
    spmm_acc(w, lane, reinterpret_cast<const uint2*>(g_H0), ax, ay, az, aw);
    store_h(reinterpret_cast<uint2*>(g_H1), w, lane, ax, ay, az, aw);
}

// Layer 2: active rows from g_list2, H1 -> H2 (stores 256*A^2*H0).
__global__ void k_spmm_act() {
    int w = (blockIdx.x * blockDim.x + threadIdx.x) >> 5;
    int lane = threadIdx.x & 31;
    if (w >= g_m2) return;
    int row = g_list2[w];
    float ax = 0.f, ay = 0.f, az = 0.f, aw = 0.f;
    spmm_acc(row, lane, reinterpret_cast<const uint2*>(g_H1), ax, ay, az, aw);
    store_h(reinterpret_cast<uint2*>(g_H2), row, lane, ax, ay, az, aw);
}

// Fused final: per query warp compute layer-3 row (A16 * H2) plus gathers of
// e_q (fp32 exact), H1[q], H2[q]; single write of out[w].
__global__ void k_final(const int* __restrict__ users, const int* __restrict__ items,
                        const float4* __restrict__ embU, const float4* __restrict__ embI,
                        float4* __restrict__ out) {
    int w = (blockIdx.x * blockDim.x + threadIdx.x) >> 5;
    int lane = threadIdx.x & 31;
    if (w >= 2 * BATCHQ) return;
    int q = q_node(users, items, w);

    // layer 3 accumulate: (16A * H2)_q = 4096 * (A^3 H0)_q
    float ax = 0.f, ay = 0.f, az = 0.f, aw = 0.f;
    spmm_acc(q, lane, reinterpret_cast<const uint2*>(g_H2), ax, ay, az, aw);

    // layer 0 exact
    const float4* p = (q < U_COUNT) ? (embU + (long long)q * 32)
                                    : (embI + (long long)(q - U_COUNT) * 32);
    float4 e = __ldg(p + lane);

    // layers 1,2 from fp16 buffers
    uint2 r1 = reinterpret_cast<const uint2*>(g_H1)[(long long)q * 32 + lane];
    uint2 r2 = reinterpret_cast<const uint2*>(g_H2)[(long long)q * 32 + lane];
    __half2 a0 = *reinterpret_cast<__half2*>(&r1.x);
    __half2 a1 = *reinterpret_cast<__half2*>(&r1.y);
    __half2 b0 = *reinterpret_cast<__half2*>(&r2.x);
    __half2 b1 = *reinterpret_cast<__half2*>(&r2.y);
    float2 f1a = __half22float2(a0), f1b = __half22float2(a1);
    float2 f2a = __half22float2(b0), f2b = __half22float2(b1);

    const float w0 = 0.25f;
    const float w1 = 0.25f / 16.0f;
    const float w2 = 0.25f / 256.0f;
    const float w3 = 0.25f / 4096.0f;

    float4 o;
    o.x = w0 * e.x + w1 * f1a.x + w2 * f2a.x + w3 * ax;
    o.y = w0 * e.y + w1 * f1a.y + w2 * f2a.y + w3 * ay;
    o.z = w0 * e.z + w1 * f1b.x + w2 * f2b.x + w3 * az;
    o.w = w0 * e.w + w1 * f1b.y + w2 * f2b.y + w3 * aw;
    out[w * 32 + lane] = o;
}

extern "C" void kernel_launch(void* const* d_in, const int* in_sizes, int n_in,
                              void* d_out, int out_size) {
    const float4* user_emb = (const float4*)d_in[0];
    const float4* item_emb = (const float4*)d_in[1];
    const float*  adj_vals = (const float*)d_in[2];
    const int*    adj_rows = (const int*)d_in[3];
    const int*    adj_cols = (const int*)d_in[4];
    const int*    users    = (const int*)d_in[5];
    const int*    items    = (const int*)d_in[6];
    float4*       out      = (float4*)d_out;

    const int T = 256;
    const int QWARP_BLOCKS = (2 * BATCHQ * 32 + T - 1) / T;
    const int SPMM_BLOCKS  = (NN * 32 + T - 1) / T;

    // CSR build + fp16 convert
    k_zero<<<(N_PAD + T - 1) / T, T>>>();
    k_convert<<<(NN * 32 + T - 1) / T, T>>>(user_emb, item_emb);
    k_hist<<<(NNZ_C + T - 1) / T, T>>>(adj_rows);
    k_scan_part<<<NBLK_SCAN, 1024>>>();
    k_scan_add<<<NBLK_SCAN, 1024>>>();
    k_scatter<<<(NNZ_C + T - 1) / T, T>>>(adj_rows, adj_cols, adj_vals);

    // Active-set construction (needs CSR)
    k_expand<<<QWARP_BLOCKS, T>>>(users, items);
    k_compact<<<(N_PAD + T - 1) / T, T>>>();

    // layer 1: H0 -> H1 (all rows)
    k_spmm_full<<<SPMM_BLOCKS, T>>>();
    // layer 2: H1 -> H2 (active rows only)
    k_spmm_act<<<SPMM_BLOCKS, T>>>();
    // fused layer-3 + all gathers -> out
    k_final<<<QWARP_BLOCKS, T>>>(users, items, user_emb, item_emb, out);
}

// round 9
// speedup vs baseline: 2.2403x; 1.0118x over previous
#include <cuda_runtime.h>
#include <cuda_fp16.h>

// ---------------------------------------------------------------------------
// GCNMixEncoder R9: R8 + grid-partition fusion for overlap:
//   kernel Z  = zero(counts/flags) || fp32->fp16 convert
//   kernel F  = expand(Q u N(Q)) || layer-1 full SpMM
// No streams, no allocation; capture-safe.
// ---------------------------------------------------------------------------

#define U_COUNT 100000
#define I_COUNT 50000
#define NN      (U_COUNT + I_COUNT)   // 150000
#define NNZ_C   1600000
#define BATCHQ  4096
#define SCAN_CHUNK 4096
#define N_PAD   151552                 // ceil(NN/4096)*4096
#define NBLK_SCAN (N_PAD / SCAN_CHUNK) // 37

#define T_BLK   256
#define ZERO_BLOCKS   (N_PAD / T_BLK)                   // 592
#define CONV_BLOCKS   ((NN * 32 + T_BLK - 1) / T_BLK)   // 18750
#define EXPAND_BLOCKS ((2 * BATCHQ * 32) / T_BLK)       // 1024
#define SPMM_BLOCKS   ((NN * 32 + T_BLK - 1) / T_BLK)   // 18750

__device__ __half g_H0[(long long)NN * 128];
__device__ __half g_H1[(long long)NN * 128];
__device__ __half g_H2[(long long)NN * 128];
__device__ int   g_counts[N_PAD];
__device__ int   g_rowptr[NN + 1];
__device__ int   g_bsums[64];
__device__ int   g_lpos[NNZ_C];        // within-row position from hist
__device__ int2  g_edges[NNZ_C];       // {col, float_as_int(16*val)}
__device__ int   g_flag[N_PAD];        // layer-2 active-row flags
__device__ int   g_list2[NN];          // compacted active rows
__device__ int   g_m2;                 // active count

// users/items may be int32 or int64 (JAX x64 ambiguity): detect on device.
__device__ __forceinline__ bool is_i64(const int* p) {
    bool z = true;
    #pragma unroll
    for (int j = 1; j < 64; j += 2) z = z && (p[j] == 0);
    return z;
}

__device__ __forceinline__ int q_node(const int* __restrict__ users,
                                      const int* __restrict__ items, int w) {
    int node;
    if (w < BATCHQ) {
        bool w64 = is_i64(users);
        node = w64 ? users[2 * w] : users[w];
    } else {
        int idx = w - BATCHQ;
        bool w64 = is_i64(items);
        node = U_COUNT + (w64 ? items[2 * idx] : items[idx]);
    }
    return max(0, min(NN - 1, node));
}

// ---------------------------------------------------------------------------
// Kernel Z: blocks [0, ZERO_BLOCKS) zero counts/flags; rest convert fp32->fp16.
// ---------------------------------------------------------------------------
__global__ void k_zero_convert(const float4* __restrict__ ue, const float4* __restrict__ ie) {
    int b = blockIdx.x;
    if (b < ZERO_BLOCKS) {
        int i = b * T_BLK + threadIdx.x;
        if (i < N_PAD) { g_counts[i] = 0; g_flag[i] = 0; }
        if (i == 0) g_m2 = 0;
        return;
    }
    int i = (b - ZERO_BLOCKS) * T_BLK + threadIdx.x;   // float4 index
    const int UQ = U_COUNT * 32;
    const int TQ = NN * 32;
    if (i >= TQ) return;
    float4 f = (i < UQ) ? __ldg(&ue[i]) : __ldg(&ie[i - UQ]);
    __half2 a = __floats2half2_rn(f.x, f.y);
    __half2 bh = __floats2half2_rn(f.z, f.w);
    uint2 o;
    o.x = *reinterpret_cast<unsigned*>(&a);
    o.y = *reinterpret_cast<unsigned*>(&bh);
    reinterpret_cast<uint2*>(g_H0)[i] = o;
}

// Histogram (2 edges/thread); atomicAdd's return is the within-row slot.
__global__ void k_hist(const int* __restrict__ rows) {
    int e = 2 * (blockIdx.x * blockDim.x + threadIdx.x);
    if (e < NNZ_C)     g_lpos[e]     = atomicAdd(&g_counts[rows[e]], 1);
    if (e + 1 < NNZ_C) g_lpos[e + 1] = atomicAdd(&g_counts[rows[e + 1]], 1);
}

// Phase 1: block-local exclusive scan of a 4096-elem chunk; total to g_bsums.
__global__ void k_scan_part() {
    __shared__ int wsum[32];
    int b = blockIdx.x, t = threadIdx.x, lane = t & 31, wid = t >> 5;
    int i0 = b * SCAN_CHUNK + t * 4;
    int4 c = *reinterpret_cast<const int4*>(&g_counts[i0]);
    int p1 = c.x;
    int p2 = p1 + c.y;
    int p3 = p2 + c.z;
    int tot = p3 + c.w;
    int v = tot;
    #pragma unroll
    for (int o = 1; o < 32; o <<= 1) {
        int n = __shfl_up_sync(0xffffffffu, v, o);
        if (lane >= o) v += n;
    }
    if (lane == 31) wsum[wid] = v;
    __syncthreads();
    if (wid == 0) {
        int wv = wsum[lane];
        #pragma unroll
        for (int o = 1; o < 32; o <<= 1) {
            int n = __shfl_up_sync(0xffffffffu, wv, o);
            if (lane >= o) wv += n;
        }
        wsum[lane] = wv;
    }
    __syncthreads();
    int warp_off = wid ? wsum[wid - 1] : 0;
    int excl = warp_off + (v - tot);
    if (i0     < NN) g_rowptr[i0]     = excl;
    if (i0 + 1 < NN) g_rowptr[i0 + 1] = excl + p1;
    if (i0 + 2 < NN) g_rowptr[i0 + 2] = excl + p2;
    if (i0 + 3 < NN) g_rowptr[i0 + 3] = excl + p3;
    if (t == 0) g_bsums[b] = wsum[31];
}

// Phase 2: add inter-block offsets.
__global__ void k_scan_add() {
    __shared__ int s_off;
    int b = blockIdx.x, t = threadIdx.x;
    if (t == 0) {
        int s = 0;
        for (int j = 0; j < b; ++j) s += g_bsums[j];
        s_off = s;
    }
    __syncthreads();
    int off = s_off;
    int i0 = b * SCAN_CHUNK + t * 4;
    #pragma unroll
    for (int k = 0; k < 4; ++k) {
        int i = i0 + k;
        if (i < NN) g_rowptr[i] += off;
    }
    if (b == 0 && t == 0) g_rowptr[NN] = NNZ_C;
}

// Atomic-free scatter: final slot = rowptr[r] + lpos[e]. Edge val scaled x16.
__global__ void k_scatter(const int* __restrict__ rows, const int* __restrict__ cols,
                          const float* __restrict__ vals) {
    int e = blockIdx.x * blockDim.x + threadIdx.x;
    if (e >= NNZ_C) return;
    int r = rows[e];
    int p = g_rowptr[r] + g_lpos[e];
    g_edges[p] = make_int2(cols[e], __float_as_int(16.0f * vals[e]));
}

// ---------------------------------------------------------------------------
// SpMM row accumulate over fp16 rows (256B), fp32 accumulate.
// (Edge values carry the x16 scale.)
// ---------------------------------------------------------------------------
__device__ __forceinline__ void spmm_acc(int row, int lane,
                                         const uint2* __restrict__ src,
                                         float& ax, float& ay, float& az, float& aw) {
    int start = g_rowptr[row], end = g_rowptr[row + 1];
    for (int base = start; base < end; base += 32) {
        int e = base + lane;
        long long ed = 0;
        if (e < end) ed = *reinterpret_cast<const long long*>(&g_edges[e]);
        int cnt = min(32, end - base);
        int j = 0;
        for (; j + 4 <= cnt; j += 4) {
            uint2 r[4];
            float vv[4];
            #pragma unroll
            for (int u = 0; u < 4; ++u) {
                long long ej = __shfl_sync(0xffffffffu, ed, j + u);
                int cj = (int)ej;
                vv[u] = __int_as_float((int)(ej >> 32));
                r[u] = __ldg(&src[(long long)cj * 32 + lane]);
            }
            #pragma unroll
            for (int u = 0; u < 4; ++u) {
                __half2 h0 = *reinterpret_cast<__half2*>(&r[u].x);
                __half2 h1 = *reinterpret_cast<__half2*>(&r[u].y);
                float2 f0 = __half22float2(h0);
                float2 f1 = __half22float2(h1);
                ax = fmaf(vv[u], f0.x, ax);
                ay = fmaf(vv[u], f0.y, ay);
                az = fmaf(vv[u], f1.x, az);
                aw = fmaf(vv[u], f1.y, aw);
            }
        }
        for (; j < cnt; ++j) {
            long long ej = __shfl_sync(0xffffffffu, ed, j);
            int cj = (int)ej;
            float vj = __int_as_float((int)(ej >> 32));
            uint2 rr = __ldg(&src[(long long)cj * 32 + lane]);
            __half2 h0 = *reinterpret_cast<__half2*>(&rr.x);
            __half2 h1 = *reinterpret_cast<__half2*>(&rr.y);
            float2 f0 = __half22float2(h0);
            float2 f1 = __half22float2(h1);
            ax = fmaf(vj, f0.x, ax);
            ay = fmaf(vj, f0.y, ay);
            az = fmaf(vj, f1.x, az);
            aw = fmaf(vj, f1.y, aw);
        }
    }
}

__device__ __forceinline__ void store_h(uint2* __restrict__ dst, int row, int lane,
                                        float ax, float ay, float az, float aw) {
    __half2 o0 = __floats2half2_rn(ax, ay);
    __half2 o1 = __floats2half2_rn(az, aw);
    uint2 o;
    o.x = *reinterpret_cast<unsigned*>(&o0);
    o.y = *reinterpret_cast<unsigned*>(&o1);
    dst[(long long)row * 32 + lane] = o;
}

// ---------------------------------------------------------------------------
// Kernel F: blocks [0, EXPAND_BLOCKS) flag Q u N(Q); rest run layer-1 SpMM
// (all rows, H0 -> H1). Expand only touches CSR + flags, so it runs
// concurrently with the SpMM under one launch.
// ---------------------------------------------------------------------------
__global__ void k_expand_spmm1(const int* __restrict__ users, const int* __restrict__ items) {
    int b = blockIdx.x;
    int lane = threadIdx.x & 31;
    if (b < EXPAND_BLOCKS) {
        int w = (b * T_BLK + threadIdx.x) >> 5;
        if (w >= 2 * BATCHQ) return;
        int node = q_node(users, items, w);
        if (lane == 0) g_flag[node] = 1;
        int s = g_rowptr[node], e = g_rowptr[node + 1];
        for (int i = s + lane; i < e; i += 32)
            g_flag[g_edges[i].x] = 1;        // races benign (all write 1)
        return;
    }
    int w = ((b - EXPAND_BLOCKS) * T_BLK + threadIdx.x) >> 5;
    if (w >= NN) return;
    float ax = 0.f, ay = 0.f, az = 0.f, aw = 0.f;
    spmm_acc(w, lane, reinterpret_cast<const uint2*>(g_H0), ax, ay, az, aw);
    store_h(reinterpret_cast<uint2*>(g_H1), w, lane, ax, ay, az, aw);
}

// Warp-aggregated compaction of g_flag -> g_list2 / g_m2.
__global__ void k_compact() {
    int i = blockIdx.x * blockDim.x + threadIdx.x;
    int lane = threadIdx.x & 31;
    int f = (i < NN) ? g_flag[i] : 0;
    unsigned m = __ballot_sync(0xffffffffu, f);
    int cnt = __popc(m);
    int pos = 0;
    if (lane == 0 && cnt) pos = atomicAdd(&g_m2, cnt);
    pos = __shfl_sync(0xffffffffu, pos, 0);
    if (f) g_list2[pos + __popc(m & ((1u << lane) - 1))] = i;
}

// Layer 2: active rows from g_list2, H1 -> H2 (stores 256*A^2*H0).
__global__ void k_spmm_act() {
    int w = (blockIdx.x * blockDim.x + threadIdx.x) >> 5;
    int lane = threadIdx.x & 31;
    if (w >= g_m2) return;
    int row = g_list2[w];
    float ax = 0.f, ay = 0.f, az = 0.f, aw = 0.f;
    spmm_acc(row, lane, reinterpret_cast<const uint2*>(g_H1), ax, ay, az, aw);
    store_h(reinterpret_cast<uint2*>(g_H2), row, lane, ax, ay, az, aw);
}

// Fused final: per query warp compute layer-3 row (16A * H2) plus gathers of
// e_q (fp32 exact), H1[q], H2[q]; single write of out[w].
__global__ void k_final(const int* __restrict__ users, const int* __restrict__ items,
                        const float4* __restrict__ embU, const float4* __restrict__ embI,
                        float4* __restrict__ out) {
    int w = (blockIdx.x * blockDim.x + threadIdx.x) >> 5;
    int lane = threadIdx.x & 31;
    if (w >= 2 * BATCHQ) return;
    int q = q_node(users, items, w);

    // layer 3 accumulate: (16A * H2)_q = 4096 * (A^3 H0)_q
    float ax = 0.f, ay = 0.f, az = 0.f, aw = 0.f;
    spmm_acc(q, lane, reinterpret_cast<const uint2*>(g_H2), ax, ay, az, aw);

    // layer 0 exact
    const float4* p = (q < U_COUNT) ? (embU + (long long)q * 32)
                                    : (embI + (long long)(q - U_COUNT) * 32);
    float4 e = __ldg(p + lane);

    // layers 1,2 from fp16 buffers
    uint2 r1 = reinterpret_cast<const uint2*>(g_H1)[(long long)q * 32 + lane];
    uint2 r2 = reinterpret_cast<const uint2*>(g_H2)[(long long)q * 32 + lane];
    __half2 a0 = *reinterpret_cast<__half2*>(&r1.x);
    __half2 a1 = *reinterpret_cast<__half2*>(&r1.y);
    __half2 b0 = *reinterpret_cast<__half2*>(&r2.x);
    __half2 b1 = *reinterpret_cast<__half2*>(&r2.y);
    float2 f1a = __half22float2(a0), f1b = __half22float2(a1);
    float2 f2a = __half22float2(b0), f2b = __half22float2(b1);

    const float w0 = 0.25f;
    const float w1 = 0.25f / 16.0f;
    const float w2 = 0.25f / 256.0f;
    const float w3 = 0.25f / 4096.0f;

    float4 o;
    o.x = w0 * e.x + w1 * f1a.x + w2 * f2a.x + w3 * ax;
    o.y = w0 * e.y + w1 * f1a.y + w2 * f2a.y + w3 * ay;
    o.z = w0 * e.z + w1 * f1b.x + w2 * f2b.x + w3 * az;
    o.w = w0 * e.w + w1 * f1b.y + w2 * f2b.y + w3 * aw;
    out[w * 32 + lane] = o;
}

extern "C" void kernel_launch(void* const* d_in, const int* in_sizes, int n_in,
                              void* d_out, int out_size) {
    const float4* user_emb = (const float4*)d_in[0];
    const float4* item_emb = (const float4*)d_in[1];
    const float*  adj_vals = (const float*)d_in[2];
    const int*    adj_rows = (const int*)d_in[3];
    const int*    adj_cols = (const int*)d_in[4];
    const int*    users    = (const int*)d_in[5];
    const int*    items    = (const int*)d_in[6];
    float4*       out      = (float4*)d_out;

    const int T = T_BLK;
    const int QWARP_BLOCKS = (2 * BATCHQ * 32 + T - 1) / T;

    // Z: zero || convert
    k_zero_convert<<<ZERO_BLOCKS + CONV_BLOCKS, T>>>(user_emb, item_emb);
    // CSR build
    k_hist<<<(NNZ_C / 2 + T - 1) / T, T>>>(adj_rows);
    k_scan_part<<<NBLK_SCAN, 1024>>>();
    k_scan_add<<<NBLK_SCAN, 1024>>>();
    k_scatter<<<(NNZ_C + T - 1) / T, T>>>(adj_rows, adj_cols, adj_vals);
    // F: expand || layer-1 SpMM (H0 -> H1)
    k_expand_spmm1<<<EXPAND_BLOCKS + SPMM_BLOCKS, T>>>(users, items);
    k_compact<<<(N_PAD + T - 1) / T, T>>>();
    // layer 2: H1 -> H2 (active rows only)
    k_spmm_act<<<SPMM_BLOCKS, T>>>();
    // fused layer-3 + all gathers -> out
    k_final<<<QWARP_BLOCKS, T>>>(users, items, user_emb, item_emb, out);
}